// round 1
// baseline (speedup 1.0000x reference)
#include <cuda_runtime.h>
#include <math.h>

#define NB   8
#define ND   768
#define NCH  3
#define NMIX 5
#define H    10
#define NS   10
#define PI2f 6.283185307179586f
#define ZITTERf 1e-4f
#define INV_TEMP 10.0f
#define NTILE1 6            // ND / 128 i-tiles in feat kernel
#define TI   16             // i-tile in out kernel

// cross-kernel scratch (tiny, __device__ globals per allocation rules)
__device__ float g_hpart[NB * NCH * NTILE1 * H];  // partial sums of relu(layer1) over i
__device__ float g_w[NB * NCH * NMIX];            // gumbel-softmax mixture weights
__device__ float g_diag[NCH];                     // zitter + clip(likerr)^2

// ---------------------------------------------------------------------------
// Kernel 1: pairwise spectral-mixture reduction over j -> feature -> layer1
// block = (b, c, i_tile of 128). Uses angle-addition for cos (accurate, 5 MUFU/pair).
// ---------------------------------------------------------------------------
__global__ void __launch_bounds__(128) feat_kernel(
    const float* __restrict__ xc, const float* __restrict__ yc,
    const float* __restrict__ mu, const float* __restrict__ inv_std,
    const float* __restrict__ W1, const float* __restrict__ b1)
{
    int bid  = blockIdx.x;
    int tile = bid % NTILE1;
    int bc   = bid / NTILE1;
    int c    = bc % NCH;
    int b    = bc / NCH;
    int tid  = threadIdx.x;

    __shared__ float xs[ND];
    __shared__ float ys[ND];
    __shared__ float ca[ND][NMIX];
    __shared__ float sa[ND][NMIX];
    __shared__ float sh_h[128][H];

    float km[NMIX], pm[NMIX];
#pragma unroll
    for (int m = 0; m < NMIX; m++) {
        float iv = inv_std[m];
        km[m] = -0.5f * PI2f * PI2f * iv * iv * 1.44269504088896341f; // log2(e) folded in
        pm[m] = PI2f * mu[m];
    }

    for (int j = tid; j < ND; j += 128) {
        float xv = xc[(b * ND + j) * NCH + c];
        xs[j] = xv;
        ys[j] = yc[(b * ND + j) * NCH + c];
#pragma unroll
        for (int m = 0; m < NMIX; m++) {
            float s, co;
            sincosf(pm[m] * xv, &s, &co);
            ca[j][m] = co;
            sa[j][m] = s;
        }
    }
    __syncthreads();

    int   i  = tile * 128 + tid;
    float xi = xs[i];
    float yi = ys[i];
    float cai[NMIX], sai[NMIX], acc[NMIX];
#pragma unroll
    for (int m = 0; m < NMIX; m++) {
        cai[m] = ca[i][m];
        sai[m] = sa[i][m];
        acc[m] = 0.f;
    }

#pragma unroll 2
    for (int j = 0; j < ND; j++) {
        float d  = xi - xs[j];
        float d2 = d * d;
        float yj = ys[j];
#pragma unroll
        for (int m = 0; m < NMIX; m++) {
            float e  = exp2f(km[m] * d2);                       // 1 MUFU EX2
            float cv = fmaf(cai[m], ca[j][m], sai[m] * sa[j][m]);
            acc[m] = fmaf(e * cv, yj, acc[m]);
        }
    }

    // tif = [feature(5), yc] -> layer1 relu
    float tif[NMIX + 1];
#pragma unroll
    for (int m = 0; m < NMIX; m++) tif[m] = acc[m] + ZITTERf * yi;
    tif[NMIX] = yi;

#pragma unroll
    for (int k = 0; k < H; k++) {
        float s = b1[k];
#pragma unroll
        for (int t = 0; t < NMIX + 1; t++) s = fmaf(W1[k * (NMIX + 1) + t], tif[t], s);
        sh_h[tid][k] = fmaxf(s, 0.f);
    }
    __syncthreads();

    // deterministic block reduction over the 128 i's of this tile
    if (tid < H) {
        float s = 0.f;
        for (int t = 0; t < 128; t++) s += sh_h[t][tid];
        g_hpart[(bc * NTILE1 + tile) * H + tid] = s;
    }
}

// ---------------------------------------------------------------------------
// Kernel 2: finish mean, MLP layers 2-5, Gumbel-softmax weights, diag. 1 warp.
// ---------------------------------------------------------------------------
__global__ void __launch_bounds__(32) mlp_kernel(
    const float* __restrict__ likerr, const float* __restrict__ unif,
    const float* __restrict__ W2, const float* __restrict__ b2,
    const float* __restrict__ W3, const float* __restrict__ b3,
    const float* __restrict__ W4, const float* __restrict__ b4,
    const float* __restrict__ W5, const float* __restrict__ b5)
{
    __shared__ float sh_h0[NB][NCH * H];
    __shared__ float sh_ll[NB][NCH * NMIX];
    int t = threadIdx.x;

    if (t < NB * NCH) {
        int b = t / NCH, c = t % NCH;
        for (int k = 0; k < H; k++) {
            float s = 0.f;
            for (int tt = 0; tt < NTILE1; tt++)
                s += g_hpart[((b * NCH + c) * NTILE1 + tt) * H + k];
            sh_h0[b][c * H + k] = s * (1.0f / ND);
        }
    }
    if (t < NCH) {
        float l = fminf(fmaxf(likerr[t], 0.1f), 1.0f);
        g_diag[t] = ZITTERf + l * l;
    }
    __syncthreads();

    if (t < NB) {
        float h2[H], h3[H], h4[H];
        for (int k = 0; k < H; k++) {
            float s = b2[k];
            for (int u = 0; u < NCH * H; u++) s = fmaf(W2[k * (NCH * H) + u], sh_h0[t][u], s);
            h2[k] = fmaxf(s, 0.f);
        }
        for (int k = 0; k < H; k++) {
            float s = b3[k];
            for (int u = 0; u < H; u++) s = fmaf(W3[k * H + u], h2[u], s);
            h3[k] = fmaxf(s, 0.f);
        }
        for (int k = 0; k < H; k++) {
            float s = b4[k];
            for (int u = 0; u < H; u++) s = fmaf(W4[k * H + u], h3[u], s);
            h4[k] = fmaxf(s, 0.f);
        }
        for (int n = 0; n < NCH * NMIX; n++) {
            float s = b5[n];
            for (int u = 0; u < H; u++) s = fmaf(W5[n * H + u], h4[u], s);
            sh_ll[t][n] = s;
        }
    }
    __syncthreads();

    if (t < NB * NCH) {
        int b = t / NCH, c = t % NCH;
        float accw[NMIX] = {0.f, 0.f, 0.f, 0.f, 0.f};
        for (int s = 0; s < NS; s++) {
            float z[NMIX], mx = -1e30f;
#pragma unroll
            for (int m = 0; m < NMIX; m++) {
                float u = unif[((b * NS + s) * NCH + c) * NMIX + m];
                float g = -logf(-logf(u + 1e-20f));
                z[m] = (g + sh_ll[b][c * NMIX + m]) * INV_TEMP;
                mx = fmaxf(mx, z[m]);
            }
            float sum = 0.f, e[NMIX];
#pragma unroll
            for (int m = 0; m < NMIX; m++) { e[m] = expf(z[m] - mx); sum += e[m]; }
            float inv = 1.f / sum;
#pragma unroll
            for (int m = 0; m < NMIX; m++) accw[m] += e[m] * inv;
        }
#pragma unroll
        for (int m = 0; m < NMIX; m++)
            g_w[(b * NCH + c) * NMIX + m] = accw[m] * (1.0f / NS);
    }
}

// ---------------------------------------------------------------------------
// Kernel 3: final weighted pairwise output. block = (b, i-tile of TI).
// Each thread owns 3 fixed j's, computes all 3 channels -> 12B contiguous store.
// ---------------------------------------------------------------------------
__global__ void __launch_bounds__(256) out_kernel(
    const float* __restrict__ xc, float* __restrict__ out,
    const float* __restrict__ mu, const float* __restrict__ inv_std)
{
    int bid  = blockIdx.x;
    int tile = bid % (ND / TI);
    int b    = bid / (ND / TI);
    int tid  = threadIdx.x;

    __shared__ float xs[NCH][ND];
    __shared__ float wsh[NCH * NMIX];
    __shared__ float dsh[NCH];

    for (int idx = tid; idx < ND * NCH; idx += 256) {
        int j = idx / NCH, c = idx % NCH;
        xs[c][j] = xc[(b * ND + j) * NCH + c];
    }
    if (tid < NCH * NMIX) wsh[tid] = g_w[b * NCH * NMIX + tid];
    if (tid < NCH)        dsh[tid] = g_diag[tid];

    float km[NMIX], pm[NMIX];
#pragma unroll
    for (int m = 0; m < NMIX; m++) {
        float iv = inv_std[m];
        km[m] = -0.5f * PI2f * PI2f * iv * iv;
        pm[m] = PI2f * mu[m];
    }
    __syncthreads();

    float w[NCH][NMIX];
#pragma unroll
    for (int c = 0; c < NCH; c++)
#pragma unroll
        for (int m = 0; m < NMIX; m++) w[c][m] = wsh[c * NMIX + m];
    float dg[NCH];
#pragma unroll
    for (int c = 0; c < NCH; c++) dg[c] = dsh[c];

    float xj[3][NCH];
#pragma unroll
    for (int jj = 0; jj < 3; jj++)
#pragma unroll
        for (int c = 0; c < NCH; c++) xj[jj][c] = xs[c][tid + 256 * jj];

    int i0 = tile * TI;
    for (int ii = 0; ii < TI; ii++) {
        int i = i0 + ii;
#pragma unroll
        for (int jj = 0; jj < 3; jj++) {
            int j = tid + 256 * jj;
            float r[NCH];
#pragma unroll
            for (int c = 0; c < NCH; c++) {
                float d   = xs[c][i] - xj[jj][c];
                float d2  = d * d;
                float acc = (i == j) ? dg[c] : 0.f;
#pragma unroll
                for (int m = 0; m < NMIX; m++) {
                    float e  = __expf(km[m] * d2);
                    float cv = __cosf(pm[m] * d);
                    acc = fmaf(e * cv, w[c][m], acc);
                }
                r[c] = acc;
            }
            float* o = out + ((size_t)(b * ND + i) * ND + j) * NCH;
            o[0] = r[0]; o[1] = r[1]; o[2] = r[2];
        }
    }
}

extern "C" void kernel_launch(void* const* d_in, const int* in_sizes, int n_in,
                              void* d_out, int out_size)
{
    const float* xc      = (const float*)d_in[0];
    const float* yc      = (const float*)d_in[1];
    const float* mu      = (const float*)d_in[2];
    const float* inv_std = (const float*)d_in[3];
    const float* likerr  = (const float*)d_in[4];
    const float* unif    = (const float*)d_in[5];
    const float* W1 = (const float*)d_in[6];  const float* b1 = (const float*)d_in[7];
    const float* W2 = (const float*)d_in[8];  const float* b2 = (const float*)d_in[9];
    const float* W3 = (const float*)d_in[10]; const float* b3 = (const float*)d_in[11];
    const float* W4 = (const float*)d_in[12]; const float* b4 = (const float*)d_in[13];
    const float* W5 = (const float*)d_in[14]; const float* b5 = (const float*)d_in[15];

    feat_kernel<<<NB * NCH * NTILE1, 128>>>(xc, yc, mu, inv_std, W1, b1);
    mlp_kernel<<<1, 32>>>(likerr, unif, W2, b2, W3, b3, W4, b4, W5, b5);
    out_kernel<<<NB * (ND / TI), 256>>>(xc, (float*)d_out, mu, inv_std);
}

// round 2
// speedup vs baseline: 1.0950x; 1.0950x over previous
#include <cuda_runtime.h>
#include <math.h>

#define NB   8
#define ND   768
#define NCH  3
#define NMIX 5
#define H    10
#define NS   10
#define PI2f 6.283185307179586f
#define ZITTERf 1e-4f
#define INV_TEMP 10.0f
#define LOG2E 1.44269504088896341f

#define NTILE1 6            // ND/128 i-tiles (feat/feat2)
#define NJC 4               // j-chunks in feat
#define JC  192             // ND/NJC
#define JT  128             // j-tile in out kernel (== blockDim)
#define IT  96              // i-tile in out kernel (ND/IT = 8)

// cross-kernel scratch (__device__ globals per allocation rules)
__device__ float g_facc[NB * NCH * ND * NJC * NMIX];  // feat partial sums (1.4MB)
__device__ float g_hpart[NB * NCH * NTILE1 * H];
__device__ float g_w[NB * NCH * NMIX];
__device__ float g_diag[NCH];

// ---------------------------------------------------------------------------
// Kernel 1: pairwise SM-kernel j-reduction, j split in NJC chunks for occupancy.
// block = (b, c, i-tile of 128, j-chunk of 192). Angle-addition cos, y folded in.
// ---------------------------------------------------------------------------
__global__ void __launch_bounds__(128) feat_kernel(
    const float* __restrict__ xc, const float* __restrict__ yc,
    const float* __restrict__ mu, const float* __restrict__ inv_std)
{
    int bid   = blockIdx.x;
    int chunk = bid % NJC;
    int r     = bid / NJC;
    int tile  = r % NTILE1;
    int bc    = r / NTILE1;
    int c     = bc % NCH;
    int b     = bc / NCH;
    int tid   = threadIdx.x;

    __shared__ float xs[JC];
    __shared__ float cay[JC][NMIX];
    __shared__ float say[JC][NMIX];

    float km2[NMIX], pm[NMIX];
#pragma unroll
    for (int m = 0; m < NMIX; m++) {
        float iv = inv_std[m];
        km2[m] = -0.5f * PI2f * PI2f * iv * iv * LOG2E;
        pm[m]  = PI2f * mu[m];
    }

    int j0 = chunk * JC;
    for (int j = tid; j < JC; j += 128) {
        float xv = xc[(b * ND + j0 + j) * NCH + c];
        float yv = yc[(b * ND + j0 + j) * NCH + c];
        xs[j] = xv;
#pragma unroll
        for (int m = 0; m < NMIX; m++) {
            float s, co;
            sincosf(pm[m] * xv, &s, &co);
            cay[j][m] = co * yv;
            say[j][m] = s * yv;
        }
    }

    int   i  = tile * 128 + tid;
    float xi = xc[(b * ND + i) * NCH + c];
    float cai[NMIX], sai[NMIX], acc[NMIX];
#pragma unroll
    for (int m = 0; m < NMIX; m++) {
        sincosf(pm[m] * xi, &sai[m], &cai[m]);
        acc[m] = 0.f;
    }
    __syncthreads();

#pragma unroll 2
    for (int j = 0; j < JC; j++) {
        float d  = xi - xs[j];
        float d2 = d * d;
#pragma unroll
        for (int m = 0; m < NMIX; m++) {
            float e = exp2f(km2[m] * d2);
            float t = fmaf(cai[m], cay[j][m], sai[m] * say[j][m]);
            acc[m] = fmaf(e, t, acc[m]);
        }
    }

    float* p = &g_facc[(((size_t)bc * ND + i) * NJC + chunk) * NMIX];
#pragma unroll
    for (int m = 0; m < NMIX; m++) p[m] = acc[m];
}

// ---------------------------------------------------------------------------
// Kernel 2: combine j-chunks, layer-1 relu, reduce over i-tile.
// ---------------------------------------------------------------------------
__global__ void __launch_bounds__(128) feat2_kernel(
    const float* __restrict__ yc,
    const float* __restrict__ W1, const float* __restrict__ b1)
{
    int bid  = blockIdx.x;
    int tile = bid % NTILE1;
    int bc   = bid / NTILE1;
    int c    = bc % NCH;
    int b    = bc / NCH;
    int tid  = threadIdx.x;
    int i    = tile * 128 + tid;

    __shared__ float sh_h[128][H];

    float yi = yc[(b * ND + i) * NCH + c];
    const float* p = &g_facc[((size_t)bc * ND + i) * NJC * NMIX];

    float tif[NMIX + 1];
#pragma unroll
    for (int m = 0; m < NMIX; m++) {
        float s = 0.f;
#pragma unroll
        for (int ch = 0; ch < NJC; ch++) s += p[ch * NMIX + m];
        tif[m] = s + ZITTERf * yi;
    }
    tif[NMIX] = yi;

#pragma unroll
    for (int k = 0; k < H; k++) {
        float s = b1[k];
#pragma unroll
        for (int t = 0; t < NMIX + 1; t++) s = fmaf(W1[k * (NMIX + 1) + t], tif[t], s);
        sh_h[tid][k] = fmaxf(s, 0.f);
    }
    __syncthreads();

    if (tid < H) {
        float s = 0.f;
        for (int t = 0; t < 128; t++) s += sh_h[t][tid];
        g_hpart[(bc * NTILE1 + tile) * H + tid] = s;
    }
}

// ---------------------------------------------------------------------------
// Kernel 3: MLP layers 2-5 + Gumbel-softmax weights + diag. 1 warp.
// ---------------------------------------------------------------------------
__global__ void __launch_bounds__(32) mlp_kernel(
    const float* __restrict__ likerr, const float* __restrict__ unif,
    const float* __restrict__ W2, const float* __restrict__ b2,
    const float* __restrict__ W3, const float* __restrict__ b3,
    const float* __restrict__ W4, const float* __restrict__ b4,
    const float* __restrict__ W5, const float* __restrict__ b5)
{
    __shared__ float sh_h0[NB][NCH * H];
    __shared__ float sh_ll[NB][NCH * NMIX];
    int t = threadIdx.x;

    if (t < NB * NCH) {
        int b = t / NCH, c = t % NCH;
        for (int k = 0; k < H; k++) {
            float s = 0.f;
            for (int tt = 0; tt < NTILE1; tt++)
                s += g_hpart[((b * NCH + c) * NTILE1 + tt) * H + k];
            sh_h0[b][c * H + k] = s * (1.0f / ND);
        }
    }
    if (t < NCH) {
        float l = fminf(fmaxf(likerr[t], 0.1f), 1.0f);
        g_diag[t] = ZITTERf + l * l;
    }
    __syncthreads();

    if (t < NB) {
        float h2[H], h3[H], h4[H];
        for (int k = 0; k < H; k++) {
            float s = b2[k];
            for (int u = 0; u < NCH * H; u++) s = fmaf(W2[k * (NCH * H) + u], sh_h0[t][u], s);
            h2[k] = fmaxf(s, 0.f);
        }
        for (int k = 0; k < H; k++) {
            float s = b3[k];
            for (int u = 0; u < H; u++) s = fmaf(W3[k * H + u], h2[u], s);
            h3[k] = fmaxf(s, 0.f);
        }
        for (int k = 0; k < H; k++) {
            float s = b4[k];
            for (int u = 0; u < H; u++) s = fmaf(W4[k * H + u], h3[u], s);
            h4[k] = fmaxf(s, 0.f);
        }
        for (int n = 0; n < NCH * NMIX; n++) {
            float s = b5[n];
            for (int u = 0; u < H; u++) s = fmaf(W5[n * H + u], h4[u], s);
            sh_ll[t][n] = s;
        }
    }
    __syncthreads();

    if (t < NB * NCH) {
        int b = t / NCH, c = t % NCH;
        float accw[NMIX] = {0.f, 0.f, 0.f, 0.f, 0.f};
        for (int s = 0; s < NS; s++) {
            float z[NMIX], mx = -1e30f;
#pragma unroll
            for (int m = 0; m < NMIX; m++) {
                float u = unif[((b * NS + s) * NCH + c) * NMIX + m];
                float g = -logf(-logf(u + 1e-20f));
                z[m] = (g + sh_ll[b][c * NMIX + m]) * INV_TEMP;
                mx = fmaxf(mx, z[m]);
            }
            float sum = 0.f, e[NMIX];
#pragma unroll
            for (int m = 0; m < NMIX; m++) { e[m] = expf(z[m] - mx); sum += e[m]; }
            float inv = 1.f / sum;
#pragma unroll
            for (int m = 0; m < NMIX; m++) accw[m] += e[m] * inv;
        }
#pragma unroll
        for (int m = 0; m < NMIX; m++)
            g_w[(b * NCH + c) * NMIX + m] = accw[m] * (1.0f / NS);
    }
}

// ---------------------------------------------------------------------------
// Kernel 4: weighted pairwise output, angle-addition cos via shared tables.
// block = (b, j-tile 128, i-tile 96). thread = one j, all 3 channels (12B store).
// ---------------------------------------------------------------------------
__global__ void __launch_bounds__(128) out_kernel(
    const float* __restrict__ xc, float* __restrict__ out,
    const float* __restrict__ mu, const float* __restrict__ inv_std)
{
    int bid = blockIdx.x;
    int it  = bid % (ND / IT);
    int r   = bid / (ND / IT);
    int jt  = r % (ND / JT);
    int b   = r / (ND / JT);
    int tid = threadIdx.x;

    __shared__ float xish[NCH][IT];
    __shared__ float cish[IT][NCH * NMIX];
    __shared__ float sish[IT][NCH * NMIX];
    __shared__ float wsh[NCH * NMIX];
    __shared__ float dsh[NCH];

    float km2[NMIX], pm[NMIX];
#pragma unroll
    for (int m = 0; m < NMIX; m++) {
        float iv = inv_std[m];
        km2[m] = -0.5f * PI2f * PI2f * iv * iv * LOG2E;
        pm[m]  = PI2f * mu[m];
    }

    if (tid < NCH * NMIX) wsh[tid] = g_w[b * NCH * NMIX + tid];
    if (tid < NCH)        dsh[tid] = g_diag[tid];

    int ibase = it * IT;
    for (int idx = tid; idx < IT * NCH; idx += 128) {
        int ii = idx / NCH, c = idx % NCH;
        xish[c][ii] = xc[(b * ND + ibase + ii) * NCH + c];
    }
    __syncthreads();

    for (int idx = tid; idx < IT * NCH * NMIX; idx += 128) {
        int ii = idx / (NCH * NMIX);
        int cm = idx % (NCH * NMIX);
        int c = cm / NMIX, m = cm % NMIX;
        float s, co;
        sincosf(pm[m] * xish[c][ii], &s, &co);
        cish[ii][cm] = co;
        sish[ii][cm] = s;
    }

    // j-side (register resident), weight folded in
    int j = jt * JT + tid;
    float xjr[NCH];
#pragma unroll
    for (int c = 0; c < NCH; c++) xjr[c] = xc[(b * ND + j) * NCH + c];

    float cjw[NCH * NMIX], sjw[NCH * NMIX];
#pragma unroll
    for (int c = 0; c < NCH; c++)
#pragma unroll
        for (int m = 0; m < NMIX; m++) {
            float s, co;
            sincosf(pm[m] * xjr[c], &s, &co);
            float w = wsh[c * NMIX + m];
            cjw[c * NMIX + m] = co * w;
            sjw[c * NMIX + m] = s * w;
        }
    float dg[NCH];
#pragma unroll
    for (int c = 0; c < NCH; c++) dg[c] = dsh[c];
    __syncthreads();

    for (int ii = 0; ii < IT; ii++) {
        int i = ibase + ii;
        float rr[NCH];
#pragma unroll
        for (int c = 0; c < NCH; c++) {
            float d   = xish[c][ii] - xjr[c];
            float d2  = d * d;
            float acc = (i == j) ? dg[c] : 0.f;
#pragma unroll
            for (int m = 0; m < NMIX; m++) {
                float e = exp2f(km2[m] * d2);
                float t = fmaf(cish[ii][c * NMIX + m], cjw[c * NMIX + m],
                               sish[ii][c * NMIX + m] * sjw[c * NMIX + m]);
                acc = fmaf(e, t, acc);
            }
            rr[c] = acc;
        }
        float* o = out + ((size_t)(b * ND + i) * ND + j) * NCH;
        o[0] = rr[0]; o[1] = rr[1]; o[2] = rr[2];
    }
}

extern "C" void kernel_launch(void* const* d_in, const int* in_sizes, int n_in,
                              void* d_out, int out_size)
{
    const float* xc      = (const float*)d_in[0];
    const float* yc      = (const float*)d_in[1];
    const float* mu      = (const float*)d_in[2];
    const float* inv_std = (const float*)d_in[3];
    const float* likerr  = (const float*)d_in[4];
    const float* unif    = (const float*)d_in[5];
    const float* W1 = (const float*)d_in[6];  const float* b1 = (const float*)d_in[7];
    const float* W2 = (const float*)d_in[8];  const float* b2 = (const float*)d_in[9];
    const float* W3 = (const float*)d_in[10]; const float* b3 = (const float*)d_in[11];
    const float* W4 = (const float*)d_in[12]; const float* b4 = (const float*)d_in[13];
    const float* W5 = (const float*)d_in[14]; const float* b5 = (const float*)d_in[15];

    feat_kernel<<<NB * NCH * NTILE1 * NJC, 128>>>(xc, yc, mu, inv_std);
    feat2_kernel<<<NB * NCH * NTILE1, 128>>>(yc, W1, b1);
    mlp_kernel<<<1, 32>>>(likerr, unif, W2, b2, W3, b3, W4, b4, W5, b5);
    out_kernel<<<NB * (ND / JT) * (ND / IT), 128>>>(xc, (float*)d_out, mu, inv_std);
}

// round 3
// speedup vs baseline: 1.2714x; 1.1611x over previous
#include <cuda_runtime.h>
#include <math.h>

#define NB   8
#define ND   768
#define NCH  3
#define NMIX 5
#define H    10
#define NS   10
#define PI2f 6.283185307179586f
#define ZITTERf 1e-4f
#define INV_TEMP 10.0f
#define LOG2E 1.44269504088896341f

#define NTILE1 6            // ND/128 i-tiles (feat/feat2)
#define NJC 8               // j-chunks in feat
#define JC  96              // ND/NJC
#define JT  256             // j-tile in out kernel (== blockDim)
#define IT  96              // i-tile in out kernel (ND/IT = 8)

#define TBLP   3968         // table entries per (b,c); 3*TBLP*4 = 47616B shared
#define TSCALE 440.0f       // entries per unit |d|  (covers |d| < 9.0)
#define TCLAMP 3965.0f

// cross-kernel scratch (__device__ globals per allocation rules)
__device__ float g_facc[NB * NCH][NJC][ND][NMIX];   // feat partials (coalesced writes)
__device__ float g_hpart[NB * NCH * NTILE1 * H];
__device__ float g_w[NB * NCH * NMIX];
__device__ float g_diag[NCH];
__device__ __align__(16) float g_ftab[NB * NCH][TBLP];

__device__ __forceinline__ float ex2f_(float x) {
    float y; asm("ex2.approx.f32 %0, %1;" : "=f"(y) : "f"(x)); return y;
}

// ---------------------------------------------------------------------------
// Kernel 1: pairwise SM-kernel j-reduction. block = (b,c,i-tile 128,j-chunk 96).
// Angle-addition cos, y folded into j-side tables, bare EX2 for the exp.
// ---------------------------------------------------------------------------
__global__ void __launch_bounds__(128) feat_kernel(
    const float* __restrict__ xc, const float* __restrict__ yc,
    const float* __restrict__ mu, const float* __restrict__ inv_std)
{
    int bid   = blockIdx.x;
    int chunk = bid % NJC;
    int r     = bid / NJC;
    int tile  = r % NTILE1;
    int bc    = r / NTILE1;
    int c     = bc % NCH;
    int b     = bc / NCH;
    int tid   = threadIdx.x;

    __shared__ float xs[JC];
    __shared__ float cay[JC][NMIX];
    __shared__ float say[JC][NMIX];

    float km2[NMIX], pm[NMIX];
#pragma unroll
    for (int m = 0; m < NMIX; m++) {
        float iv = inv_std[m];
        km2[m] = -0.5f * PI2f * PI2f * iv * iv * LOG2E;
        pm[m]  = PI2f * mu[m];
    }

    int j0 = chunk * JC;
    if (tid < JC) {
        int j = tid;
        float xv = xc[(b * ND + j0 + j) * NCH + c];
        float yv = yc[(b * ND + j0 + j) * NCH + c];
        xs[j] = xv;
#pragma unroll
        for (int m = 0; m < NMIX; m++) {
            float s, co;
            sincosf(pm[m] * xv, &s, &co);
            cay[j][m] = co * yv;
            say[j][m] = s * yv;
        }
    }

    int   i  = tile * 128 + tid;
    float xi = xc[(b * ND + i) * NCH + c];
    float cai[NMIX], sai[NMIX], acc[NMIX];
#pragma unroll
    for (int m = 0; m < NMIX; m++) {
        sincosf(pm[m] * xi, &sai[m], &cai[m]);
        acc[m] = 0.f;
    }
    __syncthreads();

#pragma unroll 2
    for (int j = 0; j < JC; j++) {
        float d  = xi - xs[j];
        float d2 = d * d;
#pragma unroll
        for (int m = 0; m < NMIX; m++) {
            float e = ex2f_(km2[m] * d2);
            float t = fmaf(cai[m], cay[j][m], sai[m] * say[j][m]);
            acc[m] = fmaf(e, t, acc[m]);
        }
    }

#pragma unroll
    for (int m = 0; m < NMIX; m++) g_facc[bc][chunk][i][m] = acc[m];
}

// ---------------------------------------------------------------------------
// Kernel 2: combine j-chunks, layer-1 relu, reduce over i-tile.
// ---------------------------------------------------------------------------
__global__ void __launch_bounds__(128) feat2_kernel(
    const float* __restrict__ yc,
    const float* __restrict__ W1, const float* __restrict__ b1)
{
    int bid  = blockIdx.x;
    int tile = bid % NTILE1;
    int bc   = bid / NTILE1;
    int c    = bc % NCH;
    int b    = bc / NCH;
    int tid  = threadIdx.x;
    int i    = tile * 128 + tid;

    __shared__ float sh_h[128][H];

    float yi = yc[(b * ND + i) * NCH + c];

    float tif[NMIX + 1];
#pragma unroll
    for (int m = 0; m < NMIX; m++) {
        float s = 0.f;
#pragma unroll
        for (int ch = 0; ch < NJC; ch++) s += g_facc[bc][ch][i][m];
        tif[m] = s + ZITTERf * yi;
    }
    tif[NMIX] = yi;

#pragma unroll
    for (int k = 0; k < H; k++) {
        float s = b1[k];
#pragma unroll
        for (int t = 0; t < NMIX + 1; t++) s = fmaf(W1[k * (NMIX + 1) + t], tif[t], s);
        sh_h[tid][k] = fmaxf(s, 0.f);
    }
    __syncthreads();

    if (tid < H) {
        float s = 0.f;
        for (int t = 0; t < 128; t++) s += sh_h[t][tid];
        g_hpart[(bc * NTILE1 + tile) * H + tid] = s;
    }
}

// ---------------------------------------------------------------------------
// Kernel 3: MLP layers 2-5 + Gumbel-softmax weights + diag. 1 warp.
// ---------------------------------------------------------------------------
__global__ void __launch_bounds__(32) mlp_kernel(
    const float* __restrict__ likerr, const float* __restrict__ unif,
    const float* __restrict__ W2, const float* __restrict__ b2,
    const float* __restrict__ W3, const float* __restrict__ b3,
    const float* __restrict__ W4, const float* __restrict__ b4,
    const float* __restrict__ W5, const float* __restrict__ b5)
{
    __shared__ float sh_h0[NB][NCH * H];
    __shared__ float sh_ll[NB][NCH * NMIX];
    int t = threadIdx.x;

    if (t < NB * NCH) {
        int b = t / NCH, c = t % NCH;
        for (int k = 0; k < H; k++) {
            float s = 0.f;
            for (int tt = 0; tt < NTILE1; tt++)
                s += g_hpart[((b * NCH + c) * NTILE1 + tt) * H + k];
            sh_h0[b][c * H + k] = s * (1.0f / ND);
        }
    }
    if (t < NCH) {
        float l = fminf(fmaxf(likerr[t], 0.1f), 1.0f);
        g_diag[t] = ZITTERf + l * l;
    }
    __syncthreads();

    if (t < NB) {
        float h2[H], h3[H], h4[H];
        for (int k = 0; k < H; k++) {
            float s = b2[k];
            for (int u = 0; u < NCH * H; u++) s = fmaf(W2[k * (NCH * H) + u], sh_h0[t][u], s);
            h2[k] = fmaxf(s, 0.f);
        }
        for (int k = 0; k < H; k++) {
            float s = b3[k];
            for (int u = 0; u < H; u++) s = fmaf(W3[k * H + u], h2[u], s);
            h3[k] = fmaxf(s, 0.f);
        }
        for (int k = 0; k < H; k++) {
            float s = b4[k];
            for (int u = 0; u < H; u++) s = fmaf(W4[k * H + u], h3[u], s);
            h4[k] = fmaxf(s, 0.f);
        }
        for (int n = 0; n < NCH * NMIX; n++) {
            float s = b5[n];
            for (int u = 0; u < H; u++) s = fmaf(W5[n * H + u], h4[u], s);
            sh_ll[t][n] = s;
        }
    }
    __syncthreads();

    if (t < NB * NCH) {
        int b = t / NCH, c = t % NCH;
        float accw[NMIX] = {0.f, 0.f, 0.f, 0.f, 0.f};
        for (int s = 0; s < NS; s++) {
            float z[NMIX], mx = -1e30f;
#pragma unroll
            for (int m = 0; m < NMIX; m++) {
                float u = unif[((b * NS + s) * NCH + c) * NMIX + m];
                float g = -logf(-logf(u + 1e-20f));
                z[m] = (g + sh_ll[b][c * NMIX + m]) * INV_TEMP;
                mx = fmaxf(mx, z[m]);
            }
            float sum = 0.f, e[NMIX];
#pragma unroll
            for (int m = 0; m < NMIX; m++) { e[m] = expf(z[m] - mx); sum += e[m]; }
            float inv = 1.f / sum;
#pragma unroll
            for (int m = 0; m < NMIX; m++) accw[m] += e[m] * inv;
        }
#pragma unroll
        for (int m = 0; m < NMIX; m++)
            g_w[(b * NCH + c) * NMIX + m] = accw[m] * (1.0f / NS);
    }
}

// ---------------------------------------------------------------------------
// Kernel 4: build per-(b,c) weighted lookup tables f(|d|).
// ---------------------------------------------------------------------------
__global__ void __launch_bounds__(256) build_f_kernel(
    const float* __restrict__ mu, const float* __restrict__ inv_std)
{
    int idx = blockIdx.x * 256 + threadIdx.x;
    if (idx >= NB * NCH * TBLP) return;
    int bc = idx / TBLP;
    int k  = idx % TBLP;
    float d = (float)k * (1.0f / TSCALE);
    float d2 = d * d;
    float acc = 0.f;
#pragma unroll
    for (int m = 0; m < NMIX; m++) {
        float iv = inv_std[m];
        float a  = -0.5f * PI2f * PI2f * iv * iv * LOG2E;
        float p  = PI2f * mu[m];
        acc = fmaf(g_w[bc * NMIX + m], ex2f_(a * d2) * cosf(p * d), acc);
    }
    g_ftab[bc][k] = acc;
}

// ---------------------------------------------------------------------------
// Kernel 5: output via shared-memory LUT. block = (b, j-tile 256, i-tile 96).
// Per element: 2 LDS + lerp. No transcendentals. Coalesced 12B stores.
// ---------------------------------------------------------------------------
__global__ void __launch_bounds__(256) out_kernel(
    const float* __restrict__ xc, float* __restrict__ out)
{
    int bid = blockIdx.x;
    int it  = bid % (ND / IT);
    int r   = bid / (ND / IT);
    int jt  = r % (ND / JT);
    int b   = r / (ND / JT);
    int tid = threadIdx.x;

    __shared__ float fs[NCH][TBLP];       // 47616 B
    __shared__ float xish[IT * NCH];      // 1152 B
    __shared__ float dsh[NCH];

    // copy this batch's 3 channel tables (contiguous in g_ftab) via float4
    {
        const float4* src = (const float4*)&g_ftab[b * NCH][0];
        float4* dst = (float4*)&fs[0][0];
        for (int q = tid; q < NCH * TBLP / 4; q += 256) dst[q] = src[q];
    }
    int ibase = it * IT;
    for (int q = tid; q < IT * NCH; q += 256)
        xish[q] = xc[(b * ND + ibase) * NCH + q];
    if (tid < NCH) dsh[tid] = g_diag[tid];

    int j = jt * JT + tid;
    float xj0 = xc[(b * ND + j) * NCH + 0];
    float xj1 = xc[(b * ND + j) * NCH + 1];
    float xj2 = xc[(b * ND + j) * NCH + 2];
    __syncthreads();

    float dg0 = dsh[0], dg1 = dsh[1], dg2 = dsh[2];

    float* o = out + ((size_t)(b * ND + ibase) * ND + j) * NCH;

    for (int ii = 0; ii < IT; ii++) {
        int i = ibase + ii;
        float t0 = fminf(fabsf(xish[ii * NCH + 0] - xj0) * TSCALE, TCLAMP);
        float t1 = fminf(fabsf(xish[ii * NCH + 1] - xj1) * TSCALE, TCLAMP);
        float t2 = fminf(fabsf(xish[ii * NCH + 2] - xj2) * TSCALE, TCLAMP);
        int k0 = (int)t0, k1 = (int)t1, k2 = (int)t2;
        float fr0 = t0 - (float)k0, fr1 = t1 - (float)k1, fr2 = t2 - (float)k2;
        float a0 = fs[0][k0], b0v = fs[0][k0 + 1];
        float a1 = fs[1][k1], b1v = fs[1][k1 + 1];
        float a2 = fs[2][k2], b2v = fs[2][k2 + 1];
        float r0 = fmaf(fr0, b0v - a0, a0);
        float r1 = fmaf(fr1, b1v - a1, a1);
        float r2 = fmaf(fr2, b2v - a2, a2);
        if (i == j) { r0 += dg0; r1 += dg1; r2 += dg2; }
        o[0] = r0; o[1] = r1; o[2] = r2;
        o += (size_t)ND * NCH;
    }
}

extern "C" void kernel_launch(void* const* d_in, const int* in_sizes, int n_in,
                              void* d_out, int out_size)
{
    const float* xc      = (const float*)d_in[0];
    const float* yc      = (const float*)d_in[1];
    const float* mu      = (const float*)d_in[2];
    const float* inv_std = (const float*)d_in[3];
    const float* likerr  = (const float*)d_in[4];
    const float* unif    = (const float*)d_in[5];
    const float* W1 = (const float*)d_in[6];  const float* b1 = (const float*)d_in[7];
    const float* W2 = (const float*)d_in[8];  const float* b2 = (const float*)d_in[9];
    const float* W3 = (const float*)d_in[10]; const float* b3 = (const float*)d_in[11];
    const float* W4 = (const float*)d_in[12]; const float* b4 = (const float*)d_in[13];
    const float* W5 = (const float*)d_in[14]; const float* b5 = (const float*)d_in[15];

    feat_kernel<<<NB * NCH * NTILE1 * NJC, 128>>>(xc, yc, mu, inv_std);
    feat2_kernel<<<NB * NCH * NTILE1, 128>>>(yc, W1, b1);
    mlp_kernel<<<1, 32>>>(likerr, unif, W2, b2, W3, b3, W4, b4, W5, b5);
    build_f_kernel<<<(NB * NCH * TBLP + 255) / 256, 256>>>(mu, inv_std);
    out_kernel<<<NB * (ND / JT) * (ND / IT), 256>>>(xc, (float*)d_out);
}

// round 4
// speedup vs baseline: 1.6191x; 1.2735x over previous
#include <cuda_runtime.h>
#include <math.h>

#define NB   8
#define ND   768
#define NCH  3
#define NMIX 5
#define H    10
#define NS   10
#define PI2f 6.283185307179586f
#define ZITTERf 1e-4f
#define INV_TEMP 10.0f
#define LOG2E 1.44269504088896341f

#define NJC 8               // j-chunks in feat
#define JC  96              // ND/NJC
#define ITILE 256           // i-range per feat block (2 i per thread)
#define NI_T  3             // ND/ITILE
#define NTILE1 6            // ND/128 i-tiles (feat2)
#define JT  256             // j-tile in out kernel (== blockDim)
#define IT  96              // i-tile in out kernel (ND/IT = 8)

#define TBLP   3968         // table entries per (b,c); 3*TBLP*4 = 47616B shared
#define TSCALE 440.0f
#define TCLAMP 3965.0f

// cross-kernel scratch (__device__ globals per allocation rules)
__device__ float g_facc[NB * NCH][NJC][NMIX][ND];   // feat partials, coalesced in i
__device__ float g_hpart[NB * NCH * NTILE1 * H];
__device__ float g_w[NB * NCH * NMIX];
__device__ float g_diag[NCH];
__device__ __align__(16) float g_ftab[NB * NCH][TBLP];

__device__ __forceinline__ float ex2f_(float x) {
    float y; asm("ex2.approx.f32 %0, %1;" : "=f"(y) : "f"(x)); return y;
}

// ---------------------------------------------------------------------------
// Kernel 1: pairwise SM-kernel j-reduction.
// block = (b, c, i-tile 256, j-chunk 96); 128 threads, 2 i's per thread.
// j-side staged as 3x float4 per j (cos*y / sin*y / x packed).
// ---------------------------------------------------------------------------
__global__ void __launch_bounds__(128) feat_kernel(
    const float* __restrict__ xc, const float* __restrict__ yc,
    const float* __restrict__ mu, const float* __restrict__ inv_std)
{
    int bid   = blockIdx.x;
    int chunk = bid % NJC;
    int r     = bid / NJC;
    int tile  = r % NI_T;
    int bc    = r / NI_T;
    int c     = bc % NCH;
    int b     = bc / NCH;
    int tid   = threadIdx.x;

    __shared__ float4 jt[JC][3];

    float km2[NMIX], pm[NMIX];
#pragma unroll
    for (int m = 0; m < NMIX; m++) {
        float iv = inv_std[m];
        km2[m] = -0.5f * PI2f * PI2f * iv * iv * LOG2E;
        pm[m]  = PI2f * mu[m];
    }

    int j0 = chunk * JC;
    if (tid < JC) {
        float xv = xc[(b * ND + j0 + tid) * NCH + c];
        float yv = yc[(b * ND + j0 + tid) * NCH + c];
        float cy[NMIX], sy[NMIX];
#pragma unroll
        for (int m = 0; m < NMIX; m++) {
            float s, co;
            __sincosf(pm[m] * xv, &s, &co);
            cy[m] = co * yv;
            sy[m] = s * yv;
        }
        jt[tid][0] = make_float4(cy[0], cy[1], cy[2], cy[3]);
        jt[tid][1] = make_float4(cy[4], sy[0], sy[1], sy[2]);
        jt[tid][2] = make_float4(sy[3], sy[4], xv, 0.f);
    }

    int i0 = tile * ITILE + tid;
    int i1 = i0 + 128;
    float xi0 = xc[(b * ND + i0) * NCH + c];
    float xi1 = xc[(b * ND + i1) * NCH + c];
    float ca0[NMIX], sa0[NMIX], ca1[NMIX], sa1[NMIX];
    float acc0[NMIX], acc1[NMIX];
#pragma unroll
    for (int m = 0; m < NMIX; m++) {
        __sincosf(pm[m] * xi0, &sa0[m], &ca0[m]);
        __sincosf(pm[m] * xi1, &sa1[m], &ca1[m]);
        acc0[m] = 0.f; acc1[m] = 0.f;
    }
    __syncthreads();

#pragma unroll 2
    for (int j = 0; j < JC; j++) {
        float4 t0 = jt[j][0];
        float4 t1 = jt[j][1];
        float4 t2 = jt[j][2];
        float cy[NMIX] = {t0.x, t0.y, t0.z, t0.w, t1.x};
        float sy[NMIX] = {t1.y, t1.z, t1.w, t2.x, t2.y};
        float xj = t2.z;
        float d0 = xi0 - xj, d20 = d0 * d0;
        float d1 = xi1 - xj, d21 = d1 * d1;
#pragma unroll
        for (int m = 0; m < NMIX; m++) {
            float e0 = ex2f_(km2[m] * d20);
            float e1 = ex2f_(km2[m] * d21);
            float v0 = fmaf(ca0[m], cy[m], sa0[m] * sy[m]);
            float v1 = fmaf(ca1[m], cy[m], sa1[m] * sy[m]);
            acc0[m] = fmaf(e0, v0, acc0[m]);
            acc1[m] = fmaf(e1, v1, acc1[m]);
        }
    }

#pragma unroll
    for (int m = 0; m < NMIX; m++) {
        g_facc[bc][chunk][m][i0] = acc0[m];
        g_facc[bc][chunk][m][i1] = acc1[m];
    }
}

// ---------------------------------------------------------------------------
// Kernel 2: combine j-chunks, layer-1 relu, reduce over i-tile.
// ---------------------------------------------------------------------------
__global__ void __launch_bounds__(128) feat2_kernel(
    const float* __restrict__ yc,
    const float* __restrict__ W1, const float* __restrict__ b1)
{
    int bid  = blockIdx.x;
    int tile = bid % NTILE1;
    int bc   = bid / NTILE1;
    int c    = bc % NCH;
    int b    = bc / NCH;
    int tid  = threadIdx.x;
    int i    = tile * 128 + tid;

    __shared__ float sh_h[128][H];

    float yi = yc[(b * ND + i) * NCH + c];

    float tif[NMIX + 1];
#pragma unroll
    for (int m = 0; m < NMIX; m++) {
        float s = 0.f;
#pragma unroll
        for (int ch = 0; ch < NJC; ch++) s += g_facc[bc][ch][m][i];
        tif[m] = s + ZITTERf * yi;
    }
    tif[NMIX] = yi;

#pragma unroll
    for (int k = 0; k < H; k++) {
        float s = b1[k];
#pragma unroll
        for (int t = 0; t < NMIX + 1; t++) s = fmaf(W1[k * (NMIX + 1) + t], tif[t], s);
        sh_h[tid][k] = fmaxf(s, 0.f);
    }
    __syncthreads();

    if (tid < H) {
        float s = 0.f;
        for (int t = 0; t < 128; t++) s += sh_h[t][tid];
        g_hpart[(bc * NTILE1 + tile) * H + tid] = s;
    }
}

// ---------------------------------------------------------------------------
// Kernel 3: MLP layers 2-5 + Gumbel-softmax weights + diag. 256 threads.
// ---------------------------------------------------------------------------
__global__ void __launch_bounds__(256) mlp_kernel(
    const float* __restrict__ likerr, const float* __restrict__ unif,
    const float* __restrict__ W2, const float* __restrict__ b2,
    const float* __restrict__ W3, const float* __restrict__ b3,
    const float* __restrict__ W4, const float* __restrict__ b4,
    const float* __restrict__ W5, const float* __restrict__ b5)
{
    __shared__ float sh_h0[NB][NCH * H];
    __shared__ float sh_a[NB][H];
    __shared__ float sh_b[NB][H];
    __shared__ float sh_ll[NB][NCH * NMIX];
    __shared__ float sh_sm[NB][NS][NCH][NMIX];
    int t = threadIdx.x;

    if (t < NB * NCH) {
        int b = t / NCH, c = t % NCH;
        for (int k = 0; k < H; k++) {
            float s = 0.f;
            for (int tt = 0; tt < NTILE1; tt++)
                s += g_hpart[((b * NCH + c) * NTILE1 + tt) * H + k];
            sh_h0[b][c * H + k] = s * (1.0f / ND);
        }
    }
    if (t < NCH) {
        float l = fminf(fmaxf(likerr[t], 0.1f), 1.0f);
        g_diag[t] = ZITTERf + l * l;
    }
    __syncthreads();

    if (t < NB * H) {                       // layer 2
        int b = t / H, k = t % H;
        float s = b2[k];
        for (int u = 0; u < NCH * H; u++) s = fmaf(W2[k * (NCH * H) + u], sh_h0[b][u], s);
        sh_a[b][k] = fmaxf(s, 0.f);
    }
    __syncthreads();
    if (t < NB * H) {                       // layer 3
        int b = t / H, k = t % H;
        float s = b3[k];
        for (int u = 0; u < H; u++) s = fmaf(W3[k * H + u], sh_a[b][u], s);
        sh_b[b][k] = fmaxf(s, 0.f);
    }
    __syncthreads();
    if (t < NB * H) {                       // layer 4
        int b = t / H, k = t % H;
        float s = b4[k];
        for (int u = 0; u < H; u++) s = fmaf(W4[k * H + u], sh_b[b][u], s);
        sh_a[b][k] = fmaxf(s, 0.f);
    }
    __syncthreads();
    if (t < NB * NCH * NMIX) {              // layer 5 -> logits
        int b = t / (NCH * NMIX), n = t % (NCH * NMIX);
        float s = b5[n];
        for (int u = 0; u < H; u++) s = fmaf(W5[n * H + u], sh_a[b][u], s);
        sh_ll[b][n] = s;
    }
    __syncthreads();

    if (t < NB * NS * NCH) {                // gumbel softmax per (b,s,c)
        int b = t / (NS * NCH);
        int rem = t % (NS * NCH);
        int s = rem / NCH, c = rem % NCH;
        float z[NMIX], mx = -1e30f;
#pragma unroll
        for (int m = 0; m < NMIX; m++) {
            float u = unif[((b * NS + s) * NCH + c) * NMIX + m];
            float g = -__logf(-__logf(u + 1e-20f));
            z[m] = (g + sh_ll[b][c * NMIX + m]) * INV_TEMP;
            mx = fmaxf(mx, z[m]);
        }
        float sum = 0.f, e[NMIX];
#pragma unroll
        for (int m = 0; m < NMIX; m++) { e[m] = __expf(z[m] - mx); sum += e[m]; }
        float inv = 1.f / sum;
#pragma unroll
        for (int m = 0; m < NMIX; m++) sh_sm[b][s][c][m] = e[m] * inv;
    }
    __syncthreads();

    if (t < NB * NCH * NMIX) {              // mean over samples
        int b = t / (NCH * NMIX);
        int cm = t % (NCH * NMIX);
        int c = cm / NMIX, m = cm % NMIX;
        float s = 0.f;
#pragma unroll
        for (int ss = 0; ss < NS; ss++) s += sh_sm[b][ss][c][m];
        g_w[(b * NCH + c) * NMIX + m] = s * (1.0f / NS);
    }
}

// ---------------------------------------------------------------------------
// Kernel 4: build per-(b,c) weighted lookup tables f(|d|). Fast-math.
// ---------------------------------------------------------------------------
__global__ void __launch_bounds__(256) build_f_kernel(
    const float* __restrict__ mu, const float* __restrict__ inv_std)
{
    int idx = blockIdx.x * 256 + threadIdx.x;
    if (idx >= NB * NCH * TBLP) return;
    int bc = idx / TBLP;
    int k  = idx % TBLP;
    float d = (float)k * (1.0f / TSCALE);
    float d2 = d * d;
    float acc = 0.f;
#pragma unroll
    for (int m = 0; m < NMIX; m++) {
        float iv = inv_std[m];
        float a  = -0.5f * PI2f * PI2f * iv * iv * LOG2E;
        float p  = PI2f * mu[m];
        acc = fmaf(g_w[bc * NMIX + m], ex2f_(a * d2) * __cosf(p * d), acc);
    }
    g_ftab[bc][k] = acc;
}

// ---------------------------------------------------------------------------
// Kernel 5: output via shared-memory LUT. block = (b, j-tile 256, i-tile 96).
// ---------------------------------------------------------------------------
__global__ void __launch_bounds__(256) out_kernel(
    const float* __restrict__ xc, float* __restrict__ out)
{
    int bid = blockIdx.x;
    int it  = bid % (ND / IT);
    int r   = bid / (ND / IT);
    int jt  = r % (ND / JT);
    int b   = r / (ND / JT);
    int tid = threadIdx.x;

    __shared__ float fs[NCH][TBLP];       // 47616 B
    __shared__ float xish[IT * NCH];
    __shared__ float dsh[NCH];

    {
        const float4* src = (const float4*)&g_ftab[b * NCH][0];
        float4* dst = (float4*)&fs[0][0];
        for (int q = tid; q < NCH * TBLP / 4; q += 256) dst[q] = src[q];
    }
    int ibase = it * IT;
    for (int q = tid; q < IT * NCH; q += 256)
        xish[q] = xc[(b * ND + ibase) * NCH + q];
    if (tid < NCH) dsh[tid] = g_diag[tid];

    int j = jt * JT + tid;
    float xj0 = xc[(b * ND + j) * NCH + 0];
    float xj1 = xc[(b * ND + j) * NCH + 1];
    float xj2 = xc[(b * ND + j) * NCH + 2];
    __syncthreads();

    float dg0 = dsh[0], dg1 = dsh[1], dg2 = dsh[2];

    float* o = out + ((size_t)(b * ND + ibase) * ND + j) * NCH;

    for (int ii = 0; ii < IT; ii++) {
        int i = ibase + ii;
        float t0 = fminf(fabsf(xish[ii * NCH + 0] - xj0) * TSCALE, TCLAMP);
        float t1 = fminf(fabsf(xish[ii * NCH + 1] - xj1) * TSCALE, TCLAMP);
        float t2 = fminf(fabsf(xish[ii * NCH + 2] - xj2) * TSCALE, TCLAMP);
        int k0 = (int)t0, k1 = (int)t1, k2 = (int)t2;
        float fr0 = t0 - (float)k0, fr1 = t1 - (float)k1, fr2 = t2 - (float)k2;
        float a0 = fs[0][k0], b0v = fs[0][k0 + 1];
        float a1 = fs[1][k1], b1v = fs[1][k1 + 1];
        float a2 = fs[2][k2], b2v = fs[2][k2 + 1];
        float r0 = fmaf(fr0, b0v - a0, a0);
        float r1 = fmaf(fr1, b1v - a1, a1);
        float r2 = fmaf(fr2, b2v - a2, a2);
        if (i == j) { r0 += dg0; r1 += dg1; r2 += dg2; }
        o[0] = r0; o[1] = r1; o[2] = r2;
        o += (size_t)ND * NCH;
    }
}

extern "C" void kernel_launch(void* const* d_in, const int* in_sizes, int n_in,
                              void* d_out, int out_size)
{
    const float* xc      = (const float*)d_in[0];
    const float* yc      = (const float*)d_in[1];
    const float* mu      = (const float*)d_in[2];
    const float* inv_std = (const float*)d_in[3];
    const float* likerr  = (const float*)d_in[4];
    const float* unif    = (const float*)d_in[5];
    const float* W1 = (const float*)d_in[6];  const float* b1 = (const float*)d_in[7];
    const float* W2 = (const float*)d_in[8];  const float* b2 = (const float*)d_in[9];
    const float* W3 = (const float*)d_in[10]; const float* b3 = (const float*)d_in[11];
    const float* W4 = (const float*)d_in[12]; const float* b4 = (const float*)d_in[13];
    const float* W5 = (const float*)d_in[14]; const float* b5 = (const float*)d_in[15];

    feat_kernel<<<NB * NCH * NI_T * NJC, 128>>>(xc, yc, mu, inv_std);
    feat2_kernel<<<NB * NCH * NTILE1, 128>>>(yc, W1, b1);
    mlp_kernel<<<1, 256>>>(likerr, unif, W2, b2, W3, b3, W4, b4, W5, b5);
    build_f_kernel<<<(NB * NCH * TBLP + 255) / 256, 256>>>(mu, inv_std);
    out_kernel<<<NB * (ND / JT) * (ND / IT), 256>>>(xc, (float*)d_out);
}

// round 6
// speedup vs baseline: 1.7756x; 1.0967x over previous
#include <cuda_runtime.h>
#include <math.h>

#define NB   8
#define ND   768
#define NCH  3
#define NMIX 5
#define H    10
#define NS   10
#define PI2f 6.283185307179586f
#define ZITTERf 1e-4f
#define INV_TEMP 10.0f
#define LOG2E 1.44269504088896341f

#define NJC 8               // j-chunks in feat
#define JC  96              // ND/NJC
#define ITILE 256           // i-range per feat block (2 i per thread)
#define NI_T  3             // ND/ITILE
#define NT2   3             // feat2 i-tiles of 256
#define JT  256             // j-tile in out kernel (== blockDim)
#define IT  48              // i-tile in out kernel (ND/IT = 16)

#define TBLP   1984         // float2 pair-entries per (b,c); 3*TBLP*8 = 47616B shared
#define TSCALE 220.0f       // entries per unit |d| (covers |d| <= 9.0)
#define TCLAMP 1982.0f
#define FUSED_BLOCKS (NB * NCH * TBLP / 256)   // 186
#define FEAT2_BLOCKS (NB * NCH * NT2)          // 72

// cross-kernel scratch (__device__ globals per allocation rules)
__device__ float g_facc[NB * NCH][NJC][NMIX][ND];   // feat partials, coalesced in i
__device__ float g_hpart[NB * NCH][NT2][H];
__device__ float g_w[NB * NCH * NMIX];
__device__ float g_diag[NCH];
__device__ __align__(16) float2 g_ftab2[NB * NCH][TBLP];
__device__ int g_cnt;
__device__ int g_flag;

__device__ __forceinline__ float ex2f_(float x) {
    float y; asm("ex2.approx.f32 %0, %1;" : "=f"(y) : "f"(x)); return y;
}

// ---------------------------------------------------------------------------
// Kernel 1: pairwise SM-kernel j-reduction.
// block = (b, c, i-tile 256, j-chunk 96); 128 threads, 2 i's per thread.
// Also resets the fused-kernel sync words (runs first every launch).
// ---------------------------------------------------------------------------
__global__ void __launch_bounds__(128) feat_kernel(
    const float* __restrict__ xc, const float* __restrict__ yc,
    const float* __restrict__ mu, const float* __restrict__ inv_std)
{
    if (blockIdx.x == 0 && threadIdx.x == 0) { g_cnt = 0; g_flag = 0; }

    int bid   = blockIdx.x;
    int chunk = bid % NJC;
    int r     = bid / NJC;
    int tile  = r % NI_T;
    int bc    = r / NI_T;
    int c     = bc % NCH;
    int b     = bc / NCH;
    int tid   = threadIdx.x;

    __shared__ float4 jt[JC][3];

    float km2[NMIX], pm[NMIX];
#pragma unroll
    for (int m = 0; m < NMIX; m++) {
        float iv = inv_std[m];
        km2[m] = -0.5f * PI2f * PI2f * iv * iv * LOG2E;
        pm[m]  = PI2f * mu[m];
    }

    int j0 = chunk * JC;
    if (tid < JC) {
        float xv = xc[(b * ND + j0 + tid) * NCH + c];
        float yv = yc[(b * ND + j0 + tid) * NCH + c];
        float cy[NMIX], sy[NMIX];
#pragma unroll
        for (int m = 0; m < NMIX; m++) {
            float s, co;
            __sincosf(pm[m] * xv, &s, &co);
            cy[m] = co * yv;
            sy[m] = s * yv;
        }
        jt[tid][0] = make_float4(cy[0], cy[1], cy[2], cy[3]);
        jt[tid][1] = make_float4(cy[4], sy[0], sy[1], sy[2]);
        jt[tid][2] = make_float4(sy[3], sy[4], xv, 0.f);
    }

    int i0 = tile * ITILE + tid;
    int i1 = i0 + 128;
    float xi0 = xc[(b * ND + i0) * NCH + c];
    float xi1 = xc[(b * ND + i1) * NCH + c];
    float ca0[NMIX], sa0[NMIX], ca1[NMIX], sa1[NMIX];
    float acc0[NMIX], acc1[NMIX];
#pragma unroll
    for (int m = 0; m < NMIX; m++) {
        __sincosf(pm[m] * xi0, &sa0[m], &ca0[m]);
        __sincosf(pm[m] * xi1, &sa1[m], &ca1[m]);
        acc0[m] = 0.f; acc1[m] = 0.f;
    }
    __syncthreads();

#pragma unroll 2
    for (int j = 0; j < JC; j++) {
        float4 t0 = jt[j][0];
        float4 t1 = jt[j][1];
        float4 t2 = jt[j][2];
        float cy[NMIX] = {t0.x, t0.y, t0.z, t0.w, t1.x};
        float sy[NMIX] = {t1.y, t1.z, t1.w, t2.x, t2.y};
        float xj = t2.z;
        float d0 = xi0 - xj, d20 = d0 * d0;
        float d1 = xi1 - xj, d21 = d1 * d1;
#pragma unroll
        for (int m = 0; m < NMIX; m++) {
            float e0 = ex2f_(km2[m] * d20);
            float e1 = ex2f_(km2[m] * d21);
            float v0 = fmaf(ca0[m], cy[m], sa0[m] * sy[m]);
            float v1 = fmaf(ca1[m], cy[m], sa1[m] * sy[m]);
            acc0[m] = fmaf(e0, v0, acc0[m]);
            acc1[m] = fmaf(e1, v1, acc1[m]);
        }
    }

#pragma unroll
    for (int m = 0; m < NMIX; m++) {
        g_facc[bc][chunk][m][i0] = acc0[m];
        g_facc[bc][chunk][m][i1] = acc1[m];
    }
}

// ---------------------------------------------------------------------------
// Kernel 2 (fused): feat2 (blocks 0..71) -> arrival counter -> block 0 runs
// MLP layers 2-5 + Gumbel-softmax + diag -> flag -> all 186 blocks build the
// per-(b,c) pair-packed lookup tables.
// ---------------------------------------------------------------------------
__global__ void __launch_bounds__(256) fused_mid_kernel(
    const float* __restrict__ yc,
    const float* __restrict__ W1, const float* __restrict__ b1,
    const float* __restrict__ likerr, const float* __restrict__ unif,
    const float* __restrict__ W2, const float* __restrict__ b2,
    const float* __restrict__ W3, const float* __restrict__ b3,
    const float* __restrict__ W4, const float* __restrict__ b4,
    const float* __restrict__ W5, const float* __restrict__ b5,
    const float* __restrict__ mu, const float* __restrict__ inv_std)
{
    int blk = blockIdx.x;
    int tid = threadIdx.x;

    __shared__ float sh_h[256][H];

    // ---- phase A: feat2 (layer-1 + partial i-reduction) on blocks 0..71 ----
    if (blk < FEAT2_BLOCKS) {
        int tile = blk % NT2;
        int bc   = blk / NT2;
        int c    = bc % NCH;
        int b    = bc / NCH;
        int i    = tile * 256 + tid;

        float yi = yc[(b * ND + i) * NCH + c];
        float tif[NMIX + 1];
#pragma unroll
        for (int m = 0; m < NMIX; m++) {
            float s = 0.f;
#pragma unroll
            for (int ch = 0; ch < NJC; ch++) s += g_facc[bc][ch][m][i];
            tif[m] = s + ZITTERf * yi;
        }
        tif[NMIX] = yi;

#pragma unroll
        for (int k = 0; k < H; k++) {
            float s = b1[k];
#pragma unroll
            for (int t = 0; t < NMIX + 1; t++) s = fmaf(W1[k * (NMIX + 1) + t], tif[t], s);
            sh_h[tid][k] = fmaxf(s, 0.f);
        }
        __syncthreads();

        if (tid < H) {
            float s = 0.f;
            for (int t = 0; t < 256; t++) s += sh_h[t][tid];
            g_hpart[bc][tile][tid] = s;
        }
        __syncthreads();
        if (tid == 0) { __threadfence(); atomicAdd(&g_cnt, 1); }
    }

    // ---- phase B: block 0 waits for all feat2 blocks, runs the MLP ----
    if (blk == 0) {
        if (tid == 0) { while (atomicAdd(&g_cnt, 0) < FEAT2_BLOCKS) {} __threadfence(); }
        __syncthreads();

        __shared__ float sh_h0[NB][NCH * H];
        __shared__ float sh_a[NB][H];
        __shared__ float sh_b[NB][H];
        __shared__ float sh_ll[NB][NCH * NMIX];
        __shared__ float sh_sm[NB][NS][NCH][NMIX];

        if (tid < NB * NCH) {
            int b = tid / NCH, c = tid % NCH;
            for (int k = 0; k < H; k++) {
                float s = 0.f;
#pragma unroll
                for (int tt = 0; tt < NT2; tt++) s += g_hpart[b * NCH + c][tt][k];
                sh_h0[b][c * H + k] = s * (1.0f / ND);
            }
        }
        if (tid < NCH) {
            float l = fminf(fmaxf(likerr[tid], 0.1f), 1.0f);
            g_diag[tid] = ZITTERf + l * l;
        }
        __syncthreads();

        if (tid < NB * H) {                       // layer 2
            int b = tid / H, k = tid % H;
            float s = b2[k];
            for (int u = 0; u < NCH * H; u++) s = fmaf(W2[k * (NCH * H) + u], sh_h0[b][u], s);
            sh_a[b][k] = fmaxf(s, 0.f);
        }
        __syncthreads();
        if (tid < NB * H) {                       // layer 3
            int b = tid / H, k = tid % H;
            float s = b3[k];
            for (int u = 0; u < H; u++) s = fmaf(W3[k * H + u], sh_a[b][u], s);
            sh_b[b][k] = fmaxf(s, 0.f);
        }
        __syncthreads();
        if (tid < NB * H) {                       // layer 4
            int b = tid / H, k = tid % H;
            float s = b4[k];
            for (int u = 0; u < H; u++) s = fmaf(W4[k * H + u], sh_b[b][u], s);
            sh_a[b][k] = fmaxf(s, 0.f);
        }
        __syncthreads();
        if (tid < NB * NCH * NMIX) {              // layer 5 -> logits
            int b = tid / (NCH * NMIX), n = tid % (NCH * NMIX);
            float s = b5[n];
            for (int u = 0; u < H; u++) s = fmaf(W5[n * H + u], sh_a[b][u], s);
            sh_ll[b][n] = s;
        }
        __syncthreads();

        if (tid < NB * NS * NCH) {                // gumbel softmax per (b,s,c)
            int b = tid / (NS * NCH);
            int rem = tid % (NS * NCH);
            int s = rem / NCH, c = rem % NCH;
            float z[NMIX], mx = -1e30f;
#pragma unroll
            for (int m = 0; m < NMIX; m++) {
                float u = unif[((b * NS + s) * NCH + c) * NMIX + m];
                float g = -__logf(-__logf(u + 1e-20f));
                z[m] = (g + sh_ll[b][c * NMIX + m]) * INV_TEMP;
                mx = fmaxf(mx, z[m]);
            }
            float sum = 0.f, e[NMIX];
#pragma unroll
            for (int m = 0; m < NMIX; m++) { e[m] = __expf(z[m] - mx); sum += e[m]; }
            float inv = 1.f / sum;
#pragma unroll
            for (int m = 0; m < NMIX; m++) sh_sm[b][s][c][m] = e[m] * inv;
        }
        __syncthreads();

        if (tid < NB * NCH * NMIX) {              // mean over samples
            int b = tid / (NCH * NMIX);
            int cm = tid % (NCH * NMIX);
            int c = cm / NMIX, m = cm % NMIX;
            float s = 0.f;
#pragma unroll
            for (int ss = 0; ss < NS; ss++) s += sh_sm[b][ss][c][m];
            g_w[(b * NCH + c) * NMIX + m] = s * (1.0f / NS);
        }
        __syncthreads();
        if (tid == 0) { __threadfence(); atomicExch(&g_flag, 1); }
    }

    // ---- phase C: all blocks wait for weights, build pair-packed tables ----
    if (tid == 0) { while (atomicAdd(&g_flag, 0) == 0) {} __threadfence(); }
    __syncthreads();

    {
        int idx = blk * 256 + tid;                // 186*256 = 47616 = 24*1984
        int bc  = idx / TBLP;
        int k   = idx % TBLP;
        float d0 = (float)k * (1.0f / TSCALE);
        float d1 = (float)(k + 1) * (1.0f / TSCALE);
        float d20 = d0 * d0, d21 = d1 * d1;
        float a0 = 0.f, a1 = 0.f;
#pragma unroll
        for (int m = 0; m < NMIX; m++) {
            float iv = inv_std[m];
            float a  = -0.5f * PI2f * PI2f * iv * iv * LOG2E;
            float p  = PI2f * mu[m];
            float w  = g_w[bc * NMIX + m];
            a0 = fmaf(w, ex2f_(a * d20) * __cosf(p * d0), a0);
            a1 = fmaf(w, ex2f_(a * d21) * __cosf(p * d1), a1);
        }
        g_ftab2[bc][k] = make_float2(a0, a1);
    }
}

// ---------------------------------------------------------------------------
// Kernel 3: output via shared pair-packed LUT. block = (b, j-tile 256, i-tile 48).
// Per element: 1 LDS.64 + lerp. Coalesced 12B stores.
// ---------------------------------------------------------------------------
__global__ void __launch_bounds__(256) out_kernel(
    const float* __restrict__ xc, float* __restrict__ out)
{
    int bid = blockIdx.x;
    int it  = bid % (ND / IT);
    int r   = bid / (ND / IT);
    int jt  = r % (ND / JT);
    int b   = r / (ND / JT);
    int tid = threadIdx.x;

    __shared__ float2 fs2[NCH * TBLP];    // 47616 B
    __shared__ float xish[IT * NCH];
    __shared__ float dsh[NCH];

    {
        const float4* src = (const float4*)&g_ftab2[b * NCH][0];
        float4* dst = (float4*)fs2;
        for (int q = tid; q < NCH * TBLP / 2; q += 256) dst[q] = src[q];
    }
    int ibase = it * IT;
    for (int q = tid; q < IT * NCH; q += 256)
        xish[q] = xc[(b * ND + ibase) * NCH + q];
    if (tid < NCH) dsh[tid] = g_diag[tid];

    int j = jt * JT + tid;
    float xj0 = xc[(b * ND + j) * NCH + 0];
    float xj1 = xc[(b * ND + j) * NCH + 1];
    float xj2 = xc[(b * ND + j) * NCH + 2];
    __syncthreads();

    float dg0 = dsh[0], dg1 = dsh[1], dg2 = dsh[2];

    float* o = out + ((size_t)(b * ND + ibase) * ND + j) * NCH;

    for (int ii = 0; ii < IT; ii++) {
        int i = ibase + ii;
        float t0 = fminf(fabsf(xish[ii * NCH + 0] - xj0) * TSCALE, TCLAMP);
        float t1 = fminf(fabsf(xish[ii * NCH + 1] - xj1) * TSCALE, TCLAMP);
        float t2 = fminf(fabsf(xish[ii * NCH + 2] - xj2) * TSCALE, TCLAMP);
        int k0 = (int)t0, k1 = (int)t1, k2 = (int)t2;
        float fr0 = t0 - (float)k0, fr1 = t1 - (float)k1, fr2 = t2 - (float)k2;
        float2 p0 = fs2[0 * TBLP + k0];
        float2 p1 = fs2[1 * TBLP + k1];
        float2 p2 = fs2[2 * TBLP + k2];
        float r0 = fmaf(fr0, p0.y - p0.x, p0.x);
        float r1 = fmaf(fr1, p1.y - p1.x, p1.x);
        float r2 = fmaf(fr2, p2.y - p2.x, p2.x);
        if (i == j) { r0 += dg0; r1 += dg1; r2 += dg2; }
        o[0] = r0; o[1] = r1; o[2] = r2;
        o += (size_t)ND * NCH;
    }
}

extern "C" void kernel_launch(void* const* d_in, const int* in_sizes, int n_in,
                              void* d_out, int out_size)
{
    const float* xc      = (const float*)d_in[0];
    const float* yc      = (const float*)d_in[1];
    const float* mu      = (const float*)d_in[2];
    const float* inv_std = (const float*)d_in[3];
    const float* likerr  = (const float*)d_in[4];
    const float* unif    = (const float*)d_in[5];
    const float* W1 = (const float*)d_in[6];  const float* b1 = (const float*)d_in[7];
    const float* W2 = (const float*)d_in[8];  const float* b2 = (const float*)d_in[9];
    const float* W3 = (const float*)d_in[10]; const float* b3 = (const float*)d_in[11];
    const float* W4 = (const float*)d_in[12]; const float* b4 = (const float*)d_in[13];
    const float* W5 = (const float*)d_in[14]; const float* b5 = (const float*)d_in[15];

    feat_kernel<<<NB * NCH * NI_T * NJC, 128>>>(xc, yc, mu, inv_std);
    fused_mid_kernel<<<FUSED_BLOCKS, 256>>>(yc, W1, b1, likerr, unif,
                                            W2, b2, W3, b3, W4, b4, W5, b5,
                                            mu, inv_std);
    out_kernel<<<NB * (ND / JT) * (ND / IT), 256>>>(xc, (float*)d_out);
}

// round 7
// speedup vs baseline: 1.8042x; 1.0161x over previous
#include <cuda_runtime.h>
#include <math.h>

#define NB   8
#define ND   768
#define NCH  3
#define NMIX 5
#define H    10
#define NS   10
#define PI2f 6.283185307179586f
#define ZITTERf 1e-4f
#define INV_TEMP 10.0f
#define LOG2E 1.44269504088896341f

#define NJC 16              // j-chunks in feat
#define JC  48              // ND/NJC
#define ITILE 256           // i-range per feat block (2 i per thread)
#define NI_T  3             // ND/ITILE
#define NT2   3             // feat2 i-tiles of 256
#define JT  256             // j-tile in out kernel (== blockDim)
#define IT  48              // i-tile in out kernel (ND/IT = 16)

#define TBLP   1984         // float2 pair-entries per (b,c); 3*TBLP*8 = 47616B shared
#define TSCALE 220.0f       // entries per unit |d| (covers |d| <= 9.0)
#define TCLAMP 1982.0f
#define FUSED_BLOCKS (NB * NCH * TBLP / 256)   // 186
#define FEAT2_BLOCKS (NB * NCH * NT2)          // 72

// cross-kernel scratch (__device__ globals per allocation rules)
__device__ float g_facc[NB * NCH][NJC][NMIX][ND];   // feat partials, coalesced in i
__device__ float g_hpart[NB * NCH][NT2][H];
__device__ float g_w[NB * NCH * NMIX];
__device__ float g_diag[NCH];
__device__ __align__(16) float2 g_ftab2[NB * NCH][TBLP];
__device__ int g_cnt;
__device__ int g_flag;

__device__ __forceinline__ float ex2f_(float x) {
    float y; asm("ex2.approx.f32 %0, %1;" : "=f"(y) : "f"(x)); return y;
}

// ---------------------------------------------------------------------------
// Kernel 1: pairwise SM-kernel j-reduction with split accumulators.
// block = (b, c, i-tile 256, j-chunk 48); 128 threads, 2 i's per thread.
// Inner loop per (i,m): MUL + EX2 + 2 FMA. i-side rotation applied after loop.
// ---------------------------------------------------------------------------
__global__ void __launch_bounds__(128) feat_kernel(
    const float* __restrict__ xc, const float* __restrict__ yc,
    const float* __restrict__ mu, const float* __restrict__ inv_std)
{
    if (blockIdx.x == 0 && threadIdx.x == 0) { g_cnt = 0; g_flag = 0; }

    int bid   = blockIdx.x;
    int chunk = bid % NJC;
    int r     = bid / NJC;
    int tile  = r % NI_T;
    int bc    = r / NI_T;
    int c     = bc % NCH;
    int b     = bc / NCH;
    int tid   = threadIdx.x;

    __shared__ float4 jt[JC][3];

    float km2[NMIX], pm[NMIX];
#pragma unroll
    for (int m = 0; m < NMIX; m++) {
        float iv = inv_std[m];
        km2[m] = -0.5f * PI2f * PI2f * iv * iv * LOG2E;
        pm[m]  = PI2f * mu[m];
    }

    int j0 = chunk * JC;
    if (tid < JC) {
        float xv = xc[(b * ND + j0 + tid) * NCH + c];
        float yv = yc[(b * ND + j0 + tid) * NCH + c];
        float cy[NMIX], sy[NMIX];
#pragma unroll
        for (int m = 0; m < NMIX; m++) {
            float s, co;
            __sincosf(pm[m] * xv, &s, &co);
            cy[m] = co * yv;
            sy[m] = s * yv;
        }
        jt[tid][0] = make_float4(cy[0], cy[1], cy[2], cy[3]);
        jt[tid][1] = make_float4(cy[4], sy[0], sy[1], sy[2]);
        jt[tid][2] = make_float4(sy[3], sy[4], xv, 0.f);
    }

    int i0 = tile * ITILE + tid;
    int i1 = i0 + 128;
    float xi0 = xc[(b * ND + i0) * NCH + c];
    float xi1 = xc[(b * ND + i1) * NCH + c];

    float A0[NMIX], B0[NMIX], A1[NMIX], B1[NMIX];
#pragma unroll
    for (int m = 0; m < NMIX; m++) { A0[m] = B0[m] = A1[m] = B1[m] = 0.f; }
    __syncthreads();

#pragma unroll 2
    for (int j = 0; j < JC; j++) {
        float4 t0 = jt[j][0];
        float4 t1 = jt[j][1];
        float4 t2 = jt[j][2];
        float cy[NMIX] = {t0.x, t0.y, t0.z, t0.w, t1.x};
        float sy[NMIX] = {t1.y, t1.z, t1.w, t2.x, t2.y};
        float xj = t2.z;
        float d0 = xi0 - xj, d20 = d0 * d0;
        float d1 = xi1 - xj, d21 = d1 * d1;
#pragma unroll
        for (int m = 0; m < NMIX; m++) {
            float e0 = ex2f_(km2[m] * d20);
            float e1 = ex2f_(km2[m] * d21);
            A0[m] = fmaf(e0, cy[m], A0[m]);
            B0[m] = fmaf(e0, sy[m], B0[m]);
            A1[m] = fmaf(e1, cy[m], A1[m]);
            B1[m] = fmaf(e1, sy[m], B1[m]);
        }
    }

    // apply i-side rotation once per (i,m)
#pragma unroll
    for (int m = 0; m < NMIX; m++) {
        float s0, c0, s1, c1;
        __sincosf(pm[m] * xi0, &s0, &c0);
        __sincosf(pm[m] * xi1, &s1, &c1);
        g_facc[bc][chunk][m][i0] = fmaf(c0, A0[m], s0 * B0[m]);
        g_facc[bc][chunk][m][i1] = fmaf(c1, A1[m], s1 * B1[m]);
    }
}

// ---------------------------------------------------------------------------
// Kernel 2 (fused): feat2 (blocks 0..71) -> arrival counter -> block 0 runs
// MLP layers 2-5 + Gumbel-softmax + diag -> flag -> all 186 blocks build the
// per-(b,c) pair-packed lookup tables.
// ---------------------------------------------------------------------------
__global__ void __launch_bounds__(256) fused_mid_kernel(
    const float* __restrict__ yc,
    const float* __restrict__ W1, const float* __restrict__ b1,
    const float* __restrict__ likerr, const float* __restrict__ unif,
    const float* __restrict__ W2, const float* __restrict__ b2,
    const float* __restrict__ W3, const float* __restrict__ b3,
    const float* __restrict__ W4, const float* __restrict__ b4,
    const float* __restrict__ W5, const float* __restrict__ b5,
    const float* __restrict__ mu, const float* __restrict__ inv_std)
{
    int blk = blockIdx.x;
    int tid = threadIdx.x;

    __shared__ float sh_h[256][H];

    // ---- phase A: feat2 (layer-1 + partial i-reduction) on blocks 0..71 ----
    if (blk < FEAT2_BLOCKS) {
        int tile = blk % NT2;
        int bc   = blk / NT2;
        int c    = bc % NCH;
        int b    = bc / NCH;
        int i    = tile * 256 + tid;

        float yi = yc[(b * ND + i) * NCH + c];
        float tif[NMIX + 1];
#pragma unroll
        for (int m = 0; m < NMIX; m++) {
            float s = 0.f;
#pragma unroll
            for (int ch = 0; ch < NJC; ch++) s += g_facc[bc][ch][m][i];
            tif[m] = s + ZITTERf * yi;
        }
        tif[NMIX] = yi;

#pragma unroll
        for (int k = 0; k < H; k++) {
            float s = b1[k];
#pragma unroll
            for (int t = 0; t < NMIX + 1; t++) s = fmaf(W1[k * (NMIX + 1) + t], tif[t], s);
            sh_h[tid][k] = fmaxf(s, 0.f);
        }
        __syncthreads();

        if (tid < H) {
            float s = 0.f;
            for (int t = 0; t < 256; t++) s += sh_h[t][tid];
            g_hpart[bc][tile][tid] = s;
        }
        __syncthreads();
        if (tid == 0) { __threadfence(); atomicAdd(&g_cnt, 1); }
    }

    // ---- phase B: block 0 waits for all feat2 blocks, runs the MLP ----
    if (blk == 0) {
        if (tid == 0) { while (atomicAdd(&g_cnt, 0) < FEAT2_BLOCKS) {} __threadfence(); }
        __syncthreads();

        __shared__ float sh_h0[NB][NCH * H];
        __shared__ float sh_a[NB][H];
        __shared__ float sh_b[NB][H];
        __shared__ float sh_ll[NB][NCH * NMIX];
        __shared__ float sh_sm[NB][NS][NCH][NMIX];

        if (tid < NB * NCH) {
            int b = tid / NCH, c = tid % NCH;
            for (int k = 0; k < H; k++) {
                float s = 0.f;
#pragma unroll
                for (int tt = 0; tt < NT2; tt++) s += g_hpart[b * NCH + c][tt][k];
                sh_h0[b][c * H + k] = s * (1.0f / ND);
            }
        }
        if (tid < NCH) {
            float l = fminf(fmaxf(likerr[tid], 0.1f), 1.0f);
            g_diag[tid] = ZITTERf + l * l;
        }
        __syncthreads();

        if (tid < NB * H) {                       // layer 2
            int b = tid / H, k = tid % H;
            float s = b2[k];
            for (int u = 0; u < NCH * H; u++) s = fmaf(W2[k * (NCH * H) + u], sh_h0[b][u], s);
            sh_a[b][k] = fmaxf(s, 0.f);
        }
        __syncthreads();
        if (tid < NB * H) {                       // layer 3
            int b = tid / H, k = tid % H;
            float s = b3[k];
            for (int u = 0; u < H; u++) s = fmaf(W3[k * H + u], sh_a[b][u], s);
            sh_b[b][k] = fmaxf(s, 0.f);
        }
        __syncthreads();
        if (tid < NB * H) {                       // layer 4
            int b = tid / H, k = tid % H;
            float s = b4[k];
            for (int u = 0; u < H; u++) s = fmaf(W4[k * H + u], sh_b[b][u], s);
            sh_a[b][k] = fmaxf(s, 0.f);
        }
        __syncthreads();
        if (tid < NB * NCH * NMIX) {              // layer 5 -> logits
            int b = tid / (NCH * NMIX), n = tid % (NCH * NMIX);
            float s = b5[n];
            for (int u = 0; u < H; u++) s = fmaf(W5[n * H + u], sh_a[b][u], s);
            sh_ll[b][n] = s;
        }
        __syncthreads();

        if (tid < NB * NS * NCH) {                // gumbel softmax per (b,s,c)
            int b = tid / (NS * NCH);
            int rem = tid % (NS * NCH);
            int s = rem / NCH, c = rem % NCH;
            float z[NMIX], mx = -1e30f;
#pragma unroll
            for (int m = 0; m < NMIX; m++) {
                float u = unif[((b * NS + s) * NCH + c) * NMIX + m];
                float g = -__logf(-__logf(u + 1e-20f));
                z[m] = (g + sh_ll[b][c * NMIX + m]) * INV_TEMP;
                mx = fmaxf(mx, z[m]);
            }
            float sum = 0.f, e[NMIX];
#pragma unroll
            for (int m = 0; m < NMIX; m++) { e[m] = __expf(z[m] - mx); sum += e[m]; }
            float inv = 1.f / sum;
#pragma unroll
            for (int m = 0; m < NMIX; m++) sh_sm[b][s][c][m] = e[m] * inv;
        }
        __syncthreads();

        if (tid < NB * NCH * NMIX) {              // mean over samples
            int b = tid / (NCH * NMIX);
            int cm = tid % (NCH * NMIX);
            int c = cm / NMIX, m = cm % NMIX;
            float s = 0.f;
#pragma unroll
            for (int ss = 0; ss < NS; ss++) s += sh_sm[b][ss][c][m];
            g_w[(b * NCH + c) * NMIX + m] = s * (1.0f / NS);
        }
        __syncthreads();
        if (tid == 0) { __threadfence(); atomicExch(&g_flag, 1); }
    }

    // ---- phase C: all blocks wait for weights, build pair-packed tables ----
    if (tid == 0) { while (atomicAdd(&g_flag, 0) == 0) {} __threadfence(); }
    __syncthreads();

    {
        int idx = blk * 256 + tid;                // 186*256 = 47616 = 24*1984
        int bc  = idx / TBLP;
        int k   = idx % TBLP;
        float d0 = (float)k * (1.0f / TSCALE);
        float d1 = (float)(k + 1) * (1.0f / TSCALE);
        float d20 = d0 * d0, d21 = d1 * d1;
        float a0 = 0.f, a1 = 0.f;
#pragma unroll
        for (int m = 0; m < NMIX; m++) {
            float iv = inv_std[m];
            float a  = -0.5f * PI2f * PI2f * iv * iv * LOG2E;
            float p  = PI2f * mu[m];
            float w  = g_w[bc * NMIX + m];
            a0 = fmaf(w, ex2f_(a * d20) * __cosf(p * d0), a0);
            a1 = fmaf(w, ex2f_(a * d21) * __cosf(p * d1), a1);
        }
        g_ftab2[bc][k] = make_float2(a0, a1);
    }
}

// ---------------------------------------------------------------------------
// Kernel 3: output via shared pair-packed LUT. block = (b, j-tile 256, i-tile 48).
// Per element: 1 LDS.64 + lerp. Coalesced 12B stores.
// ---------------------------------------------------------------------------
__global__ void __launch_bounds__(256) out_kernel(
    const float* __restrict__ xc, float* __restrict__ out)
{
    int bid = blockIdx.x;
    int it  = bid % (ND / IT);
    int r   = bid / (ND / IT);
    int jt  = r % (ND / JT);
    int b   = r / (ND / JT);
    int tid = threadIdx.x;

    __shared__ float2 fs2[NCH * TBLP];    // 47616 B
    __shared__ float xish[IT * NCH];
    __shared__ float dsh[NCH];

    {
        const float4* src = (const float4*)&g_ftab2[b * NCH][0];
        float4* dst = (float4*)fs2;
        for (int q = tid; q < NCH * TBLP / 2; q += 256) dst[q] = src[q];
    }
    int ibase = it * IT;
    for (int q = tid; q < IT * NCH; q += 256)
        xish[q] = xc[(b * ND + ibase) * NCH + q];
    if (tid < NCH) dsh[tid] = g_diag[tid];

    int j = jt * JT + tid;
    float xj0 = xc[(b * ND + j) * NCH + 0];
    float xj1 = xc[(b * ND + j) * NCH + 1];
    float xj2 = xc[(b * ND + j) * NCH + 2];
    __syncthreads();

    float dg0 = dsh[0], dg1 = dsh[1], dg2 = dsh[2];

    float* o = out + ((size_t)(b * ND + ibase) * ND + j) * NCH;

    for (int ii = 0; ii < IT; ii++) {
        int i = ibase + ii;
        float t0 = fminf(fabsf(xish[ii * NCH + 0] - xj0) * TSCALE, TCLAMP);
        float t1 = fminf(fabsf(xish[ii * NCH + 1] - xj1) * TSCALE, TCLAMP);
        float t2 = fminf(fabsf(xish[ii * NCH + 2] - xj2) * TSCALE, TCLAMP);
        int k0 = (int)t0, k1 = (int)t1, k2 = (int)t2;
        float fr0 = t0 - (float)k0, fr1 = t1 - (float)k1, fr2 = t2 - (float)k2;
        float2 p0 = fs2[0 * TBLP + k0];
        float2 p1 = fs2[1 * TBLP + k1];
        float2 p2 = fs2[2 * TBLP + k2];
        float r0 = fmaf(fr0, p0.y - p0.x, p0.x);
        float r1 = fmaf(fr1, p1.y - p1.x, p1.x);
        float r2 = fmaf(fr2, p2.y - p2.x, p2.x);
        if (i == j) { r0 += dg0; r1 += dg1; r2 += dg2; }
        o[0] = r0; o[1] = r1; o[2] = r2;
        o += (size_t)ND * NCH;
    }
}

extern "C" void kernel_launch(void* const* d_in, const int* in_sizes, int n_in,
                              void* d_out, int out_size)
{
    const float* xc      = (const float*)d_in[0];
    const float* yc      = (const float*)d_in[1];
    const float* mu      = (const float*)d_in[2];
    const float* inv_std = (const float*)d_in[3];
    const float* likerr  = (const float*)d_in[4];
    const float* unif    = (const float*)d_in[5];
    const float* W1 = (const float*)d_in[6];  const float* b1 = (const float*)d_in[7];
    const float* W2 = (const float*)d_in[8];  const float* b2 = (const float*)d_in[9];
    const float* W3 = (const float*)d_in[10]; const float* b3 = (const float*)d_in[11];
    const float* W4 = (const float*)d_in[12]; const float* b4 = (const float*)d_in[13];
    const float* W5 = (const float*)d_in[14]; const float* b5 = (const float*)d_in[15];

    feat_kernel<<<NB * NCH * NI_T * NJC, 128>>>(xc, yc, mu, inv_std);
    fused_mid_kernel<<<FUSED_BLOCKS, 256>>>(yc, W1, b1, likerr, unif,
                                            W2, b2, W3, b3, W4, b4, W5, b5,
                                            mu, inv_std);
    out_kernel<<<NB * (ND / JT) * (ND / IT), 256>>>(xc, (float*)d_out);
}